// round 1
// baseline (speedup 1.0000x reference)
#include <cuda_runtime.h>
#include <cuda_fp16.h>

// Problem constants
#define B_   64
#define T_   2048
#define D_   128
#define F_   128
#define G4   512   // 4*F

// Scratch for precomputed input projection Zpre = X @ Wi + b  (256 MB)
__device__ float g_zpre[(size_t)B_ * T_ * G4];

// ---------------------------------------------------------------------------
// Kernel A: Zpre = X @ Wi + b
// X: (B*T, 128) row-major, Wi: (128, 512), Zpre: (B*T, 512)
// Tiled fp32 GEMM: 128x128 tile, K-chunks of 32, 256 threads, 8x8 per thread.
// ---------------------------------------------------------------------------
#define TM  128
#define TN  128
#define TKA 32

__global__ __launch_bounds__(256) void gemm_xwi(const float* __restrict__ X,
                                                const float* __restrict__ Wi,
                                                const float* __restrict__ bias) {
    __shared__ float xs[TKA][TM];   // transposed: xs[k][m]
    __shared__ float ws[TKA][TN];
    const int mblk = blockIdx.x * TM;
    const int nblk = blockIdx.y * TN;
    const int tid  = threadIdx.x;
    const int tx   = tid & 15;   // 16 n-groups
    const int ty   = tid >> 4;   // 16 m-groups

    float acc[8][8];
#pragma unroll
    for (int i = 0; i < 8; i++)
#pragma unroll
        for (int j = 0; j < 8; j++) acc[i][j] = 0.f;

    for (int k0 = 0; k0 < D_; k0 += TKA) {
        // Load X tile (transpose into xs[k][m]). 1024 float4 over 256 threads.
#pragma unroll
        for (int it = 0; it < 4; it++) {
            int i  = tid + it * 256;
            int m  = i >> 3;       // 8 float4 per row of 32 k
            int kq = i & 7;
            float4 v = *(const float4*)(X + (size_t)(mblk + m) * D_ + k0 + kq * 4);
            xs[kq * 4 + 0][m] = v.x;
            xs[kq * 4 + 1][m] = v.y;
            xs[kq * 4 + 2][m] = v.z;
            xs[kq * 4 + 3][m] = v.w;
        }
        // Load Wi tile. 1024 float4 over 256 threads.
#pragma unroll
        for (int it = 0; it < 4; it++) {
            int i  = tid + it * 256;
            int k  = i >> 5;       // 32 float4 per row of 128 n
            int nq = i & 31;
            *(float4*)&ws[k][nq * 4] =
                *(const float4*)(Wi + (size_t)(k0 + k) * G4 + nblk + nq * 4);
        }
        __syncthreads();

#pragma unroll 8
        for (int k = 0; k < TKA; k++) {
            float a[8], bv[8];
            *(float4*)&a[0]  = *(float4*)&xs[k][ty * 8];
            *(float4*)&a[4]  = *(float4*)&xs[k][ty * 8 + 4];
            *(float4*)&bv[0] = *(float4*)&ws[k][tx * 8];
            *(float4*)&bv[4] = *(float4*)&ws[k][tx * 8 + 4];
#pragma unroll
            for (int i = 0; i < 8; i++)
#pragma unroll
                for (int j = 0; j < 8; j++) acc[i][j] = fmaf(a[i], bv[j], acc[i][j]);
        }
        __syncthreads();
    }

#pragma unroll
    for (int i = 0; i < 8; i++) {
        int row = mblk + ty * 8 + i;
        float* zr = g_zpre + (size_t)row * G4 + nblk + tx * 8;
#pragma unroll
        for (int j = 0; j < 8; j++) zr[j] = acc[i][j] + bias[nblk + tx * 8 + j];
    }
}

// ---------------------------------------------------------------------------
// Kernel B: persistent recurrent LSTM. One CTA per batch row (64 CTAs),
// 1024 threads. Wh stored as fp16 in shared (128 KB); h, c, accumulation fp32.
// Per step: z_half = h @ Wh (split 8 col-groups x 4 k-quarters across 32 warps),
// cross-warp reduce via shared, 128-thread gate epilogue.
// ---------------------------------------------------------------------------
#define SMEM_W_BYTES   (128 * 512 * 2)            // 131072
#define SMEM_P_OFF     SMEM_W_BYTES
#define SMEM_P_BYTES   (4 * 512 * 4)              // 8192
#define SMEM_H_OFF     (SMEM_P_OFF + SMEM_P_BYTES)
#define SMEM_B_BYTES   (SMEM_H_OFF + 128 * 4)     // 139776

__device__ __forceinline__ float sigm(float x) {
    return __fdividef(1.f, 1.f + __expf(-x));
}
__device__ __forceinline__ float tanh_f(float x) {
    float e = __expf(-2.f * fabsf(x));
    float r = __fdividef(1.f - e, 1.f + e);
    return copysignf(r, x);
}

__global__ __launch_bounds__(1024, 1) void lstm_rec(const float* __restrict__ Wh,
                                                    const float* __restrict__ h0,
                                                    const float* __restrict__ c0,
                                                    float* __restrict__ out) {
    extern __shared__ unsigned char smem[];
    half*  Ws   = (half*)smem;                      // [128][512] k-major, fp16
    float* part = (float*)(smem + SMEM_P_OFF);      // [4][512] k-partials
    float* hs   = (float*)(smem + SMEM_H_OFF);      // [128] hidden state fp32

    const int b   = blockIdx.x;
    const int tid = threadIdx.x;

    // Load + convert Wh to fp16 in shared (same k-major layout as global).
    for (int i = tid; i < 128 * 512; i += 1024)
        Ws[i] = __float2half_rn(Wh[i]);

    float c_reg = 0.f;
    if (tid < 128) {
        hs[tid] = h0[b * F_ + tid];
        c_reg   = c0[b * F_ + tid];
    }
    __syncthreads();

    // Warp work assignment: warp w -> k-quarter kq = w>>3, col-group cg = w&7.
    // Lane l handles columns cg*64 + 2l, cg*64 + 2l + 1 via half2 loads
    // (conflict-free: bank = l).
    const int w  = tid >> 5, l = tid & 31;
    const int kq = w >> 3;
    const int cg = w & 7;
    const int kbase = kq * 32;
    const half2* wp = (const half2*)Ws + (size_t)kbase * 256 + cg * 32 + l;
    float2* pout = (float2*)part + kq * 256 + cg * 32 + l;

    const int m = tid;  // epilogue index for tid < 128
    const float* zp_row  = g_zpre + (size_t)b * T_ * G4;
    float*       out_row = out    + (size_t)b * T_ * F_;

    for (int t = 0; t < T_; t++) {
        // Prefetch this step's input-projection values (consumed after bar,
        // latency hidden under the GEMV).
        float zp0 = 0.f, zp1 = 0.f, zp2 = 0.f, zp3 = 0.f;
        if (tid < 128) {
            const float* zp = zp_row + (size_t)t * G4 + m;
            zp0 = __ldg(zp);
            zp1 = __ldg(zp + 128);
            zp2 = __ldg(zp + 256);
            zp3 = __ldg(zp + 384);
        }

        // GEMV partial: acc over this warp's 32-k slice for 2 columns.
        float acc0 = 0.f, acc1 = 0.f;
#pragma unroll
        for (int kk = 0; kk < 32; kk += 4) {
            float4 h4 = *(const float4*)(hs + kbase + kk);
            {
                float2 wf = __half22float2(wp[(kk + 0) * 256]);
                acc0 = fmaf(h4.x, wf.x, acc0); acc1 = fmaf(h4.x, wf.y, acc1);
            }
            {
                float2 wf = __half22float2(wp[(kk + 1) * 256]);
                acc0 = fmaf(h4.y, wf.x, acc0); acc1 = fmaf(h4.y, wf.y, acc1);
            }
            {
                float2 wf = __half22float2(wp[(kk + 2) * 256]);
                acc0 = fmaf(h4.z, wf.x, acc0); acc1 = fmaf(h4.z, wf.y, acc1);
            }
            {
                float2 wf = __half22float2(wp[(kk + 3) * 256]);
                acc0 = fmaf(h4.w, wf.x, acc0); acc1 = fmaf(h4.w, wf.y, acc1);
            }
        }
        *pout = make_float2(acc0, acc1);
        __syncthreads();

        // Epilogue: 128 threads, one per hidden unit. Gate order i,f,g,o.
        if (tid < 128) {
            float zi = part[       m] + part[ 512 + m] + part[1024 + m] + part[1536 + m] + zp0;
            float zf = part[128  + m] + part[ 640 + m] + part[1152 + m] + part[1664 + m] + zp1;
            float zg = part[256  + m] + part[ 768 + m] + part[1280 + m] + part[1792 + m] + zp2;
            float zo = part[384  + m] + part[ 896 + m] + part[1408 + m] + part[1920 + m] + zp3;
            float ig = sigm(zi);
            float fg = sigm(zf);
            float gg = tanh_f(zg);
            float og = sigm(zo);
            float cn = fmaf(fg, c_reg, ig * gg);
            c_reg = cn;
            float hn = og * tanh_f(cn);
            hs[m] = hn;
            out_row[(size_t)t * F_ + m] = hn;
        }
        __syncthreads();
    }
}

// ---------------------------------------------------------------------------
// kernel_launch: inputs in metadata order x, h0, c0, Wi, Wh, b.
// ---------------------------------------------------------------------------
extern "C" void kernel_launch(void* const* d_in, const int* in_sizes, int n_in,
                              void* d_out, int out_size) {
    const float* x    = (const float*)d_in[0];  // (64, 2048, 128)
    const float* h0   = (const float*)d_in[1];  // (64, 128)
    const float* c0   = (const float*)d_in[2];  // (64, 128)
    const float* Wi   = (const float*)d_in[3];  // (128, 512)
    const float* Wh   = (const float*)d_in[4];  // (128, 512)
    const float* bias = (const float*)d_in[5];  // (512)
    float* out = (float*)d_out;                 // (64, 2048, 128)

    // Allow 136.5 KB dynamic shared for the recurrent kernel (idempotent).
    cudaFuncSetAttribute(lstm_rec, cudaFuncAttributeMaxDynamicSharedMemorySize,
                         SMEM_B_BYTES);

    // Input projection: (131072 x 128) @ (128 x 512) + b  -> g_zpre
    gemm_xwi<<<dim3((B_ * T_) / TM, G4 / TN), 256>>>(x, Wi, bias);

    // Recurrence: 64 persistent CTAs, one per batch row.
    lstm_rec<<<B_, 1024, SMEM_B_BYTES>>>(Wh, h0, c0, out);
}

// round 8
// speedup vs baseline: 1.8431x; 1.8431x over previous
#include <cuda_runtime.h>
#include <cuda_fp16.h>

// Problem constants
#define B_   64
#define T_   2048
#define D_   128
#define F_   128
#define G4   512   // 4*F

// Scratch for precomputed input projection Zpre = X @ Wi + b  (256 MB)
__device__ float g_zpre[(size_t)B_ * T_ * G4];

__device__ __forceinline__ void mma16816(float& d0, float& d1, float& d2, float& d3,
                                         unsigned a0, unsigned a1, unsigned a2, unsigned a3,
                                         unsigned b0, unsigned b1) {
    asm volatile(
        "mma.sync.aligned.m16n8k16.row.col.f32.f16.f16.f32 "
        "{%0,%1,%2,%3}, {%4,%5,%6,%7}, {%8,%9}, {%0,%1,%2,%3};\n"
        : "+f"(d0), "+f"(d1), "+f"(d2), "+f"(d3)
        : "r"(a0), "r"(a1), "r"(a2), "r"(a3), "r"(b0), "r"(b1));
}

// ---------------------------------------------------------------------------
// Kernel A: Zpre = X @ Wi + b via fp16 HMMA (fp32 accumulate).
// CTA: 256 threads = 8 warps (4m x 2n), tile 128m x 128n, K=128 one shot.
// Smem: As[m][k], Bs[n][k] (Wi transposed), both padded to 136-half rows
// so fragment loads are bank-conflict-free (bank = 4g+t+8kc, distinct/lane).
// ---------------------------------------------------------------------------
#define ASTRIDE 136                       // halves per row (128 + 8 pad)
#define GEMM_SMEM (2 * 128 * ASTRIDE * 2) // 69632 bytes

__global__ __launch_bounds__(256) void gemm_xwi_h(const float* __restrict__ X,
                                                  const float* __restrict__ Wi,
                                                  const float* __restrict__ bias) {
    extern __shared__ __half sm[];
    __half* As = sm;                   // [128][ASTRIDE]  (m, k)
    __half* Bs = sm + 128 * ASTRIDE;   // [128][ASTRIDE]  (n, k)  = Wi^T
    const int mblk = blockIdx.x * 128;
    const int nblk = blockIdx.y * 128;
    const int tid  = threadIdx.x;

    // Load X tile (fp32 -> fp16), k-contiguous rows.
#pragma unroll
    for (int i = 0; i < 16; i++) {
        int f4 = tid + i * 256;        // 4096 float4 total
        int m  = f4 >> 5;              // 32 float4 per row
        int q  = f4 & 31;
        float4 v = *(const float4*)(X + (size_t)(mblk + m) * D_ + q * 4);
        __half2 h0 = __floats2half2_rn(v.x, v.y);
        __half2 h1 = __floats2half2_rn(v.z, v.w);
        uint2 u; u.x = *(unsigned*)&h0; u.y = *(unsigned*)&h1;
        *(uint2*)(As + m * ASTRIDE + q * 4) = u;
    }
    // Load Wi tile transposed: Bs[n][k] = Wi[k][nblk + n].
#pragma unroll
    for (int i = 0; i < 16; i++) {
        int f4 = tid + i * 256;
        int k  = f4 >> 5;
        int q  = f4 & 31;
        float4 v = *(const float4*)(Wi + (size_t)k * G4 + nblk + q * 4);
        Bs[(q * 4 + 0) * ASTRIDE + k] = __float2half_rn(v.x);
        Bs[(q * 4 + 1) * ASTRIDE + k] = __float2half_rn(v.y);
        Bs[(q * 4 + 2) * ASTRIDE + k] = __float2half_rn(v.z);
        Bs[(q * 4 + 3) * ASTRIDE + k] = __float2half_rn(v.w);
    }
    __syncthreads();

    const int w  = tid >> 5, l = tid & 31;
    const int wm = w >> 1;             // 0..3 (m quadrant, 32 rows)
    const int wn = w & 1;              // 0..1 (n half, 64 cols)
    const int g  = l >> 2, t = l & 3;

    float acc[2][8][4];
#pragma unroll
    for (int ms = 0; ms < 2; ms++)
#pragma unroll
        for (int ns = 0; ns < 8; ns++)
#pragma unroll
            for (int j = 0; j < 4; j++) acc[ms][ns][j] = 0.f;

    const unsigned* As2 = (const unsigned*)As;   // half2 words, row stride 68
    const unsigned* Bs2 = (const unsigned*)Bs;
#define HSTR (ASTRIDE / 2)

#pragma unroll
    for (int kc = 0; kc < 8; kc++) {
        const int kw = kc * 8 + t;     // half2 word offset within a row
        unsigned a[2][4];
#pragma unroll
        for (int ms = 0; ms < 2; ms++) {
            int r = wm * 32 + ms * 16 + g;
            a[ms][0] = As2[(size_t)r * HSTR + kw];           // row g,   k 0-7
            a[ms][1] = As2[(size_t)(r + 8) * HSTR + kw];     // row g+8, k 0-7
            a[ms][2] = As2[(size_t)r * HSTR + kw + 4];       // row g,   k 8-15
            a[ms][3] = As2[(size_t)(r + 8) * HSTR + kw + 4]; // row g+8, k 8-15
        }
#pragma unroll
        for (int ns = 0; ns < 8; ns++) {
            int n = wn * 64 + ns * 8 + g;
            unsigned b0 = Bs2[(size_t)n * HSTR + kw];
            unsigned b1 = Bs2[(size_t)n * HSTR + kw + 4];
#pragma unroll
            for (int ms = 0; ms < 2; ms++)
                mma16816(acc[ms][ns][0], acc[ms][ns][1], acc[ms][ns][2], acc[ms][ns][3],
                         a[ms][0], a[ms][1], a[ms][2], a[ms][3], b0, b1);
        }
    }

    // Epilogue: D frag {d0,d1}=row g cols 2t,2t+1; {d2,d3}=row g+8.
#pragma unroll
    for (int ms = 0; ms < 2; ms++) {
        int r0 = mblk + wm * 32 + ms * 16 + g;
#pragma unroll
        for (int ns = 0; ns < 8; ns++) {
            int col = nblk + wn * 64 + ns * 8 + 2 * t;
            float2 bv = *(const float2*)(bias + col);
            float2 o0 = make_float2(acc[ms][ns][0] + bv.x, acc[ms][ns][1] + bv.y);
            float2 o1 = make_float2(acc[ms][ns][2] + bv.x, acc[ms][ns][3] + bv.y);
            *(float2*)(g_zpre + (size_t)r0 * G4 + col)       = o0;
            *(float2*)(g_zpre + (size_t)(r0 + 8) * G4 + col) = o1;
        }
    }
}

// ---------------------------------------------------------------------------
// Kernel B: persistent recurrent LSTM using HMMA (R2 design, audited).
// One CTA per batch row (64 CTAs), 512 threads = 16 warps.
// Wh lives in REGISTERS as fp16 B-fragments (loaded once).
// ---------------------------------------------------------------------------

__device__ __forceinline__ float sigm(float x) {
    return __fdividef(1.f, 1.f + __expf(-x));
}
__device__ __forceinline__ float tanh_f(float x) {
    float e = __expf(-2.f * fabsf(x));
    float r = __fdividef(1.f - e, 1.f + e);
    return copysignf(r, x);
}

__global__ __launch_bounds__(512, 1) void lstm_rec(const float* __restrict__ Wh,
                                                   const float* __restrict__ h0,
                                                   const float* __restrict__ c0,
                                                   float* __restrict__ out) {
    __shared__ float act[G4];                // activated gate values, by column
    __shared__ __align__(16) __half hs[F_];  // hidden state, fp16

    const int b   = blockIdx.x;
    const int tid = threadIdx.x;
    const int w   = tid >> 5;          // warp 0..15
    const int l   = tid & 31;          // lane
    const int t4  = l & 3;
    const int gid = l >> 2;

    // ---- Load Wh into register-resident B fragments (fp32 -> fp16) ----
    // Warp w owns columns [w*32, w*32+32) = 4 n-tiles of 8.
    unsigned b0r[4][8], b1r[4][8];
#pragma unroll
    for (int tt = 0; tt < 4; tt++) {
        const int col = w * 32 + tt * 8 + gid;
#pragma unroll
        for (int kc = 0; kc < 8; kc++) {
            const int k0 = kc * 16 + 2 * t4;
            __half2 p0 = __floats2half2_rn(Wh[(size_t)k0 * G4 + col],
                                           Wh[(size_t)(k0 + 1) * G4 + col]);
            __half2 p1 = __floats2half2_rn(Wh[(size_t)(k0 + 8) * G4 + col],
                                           Wh[(size_t)(k0 + 9) * G4 + col]);
            b0r[tt][kc] = *(unsigned*)&p0;
            b1r[tt][kc] = *(unsigned*)&p1;
        }
    }

    float c_reg = 0.f;
    if (tid < F_) {
        hs[tid] = __float2half_rn(h0[b * F_ + tid]);
        c_reg   = c0[b * F_ + tid];
    }
    __syncthreads();

    const unsigned* hs2 = (const unsigned*)hs;   // 64 half2 words
    const float* zp_base = g_zpre + (size_t)b * T_ * G4;
    float*       out_row = out    + (size_t)b * T_ * F_;

    const int mycol = w * 32 + l;
    const int tilesel0 = (l >> 3) & 1;
    const int tilesel1 = (l >> 4) & 1;
    const int subsel   = l & 1;
    const int srclane  = (l & 7) >> 1;

    float zp_cur = __ldg(zp_base + mycol);

    for (int t = 0; t < T_; t++) {
        const int tn = (t + 1 < T_) ? (t + 1) : t;
        float zp_next = __ldg(zp_base + (size_t)tn * G4 + mycol);

        // ---- z = h @ Wh (row 0 of D) ----
        float d0[4], d1[4], d2[4], d3[4];
#pragma unroll
        for (int tt = 0; tt < 4; tt++) { d0[tt] = 0.f; d1[tt] = 0.f; d2[tt] = 0.f; d3[tt] = 0.f; }

#pragma unroll
        for (int kc = 0; kc < 8; kc++) {
            unsigned a0 = hs2[kc * 8 + t4];
            unsigned a2 = hs2[kc * 8 + 4 + t4];
#pragma unroll
            for (int tt = 0; tt < 4; tt++)
                mma16816(d0[tt], d1[tt], d2[tt], d3[tt], a0, a0, a2, a2,
                         b0r[tt][kc], b1r[tt][kc]);
        }

        // ---- Route row-0 z values: lane j gets column w*32 + j ----
        float g0_0 = __shfl_sync(0xffffffffu, d0[0], srclane);
        float g1_0 = __shfl_sync(0xffffffffu, d1[0], srclane);
        float g0_1 = __shfl_sync(0xffffffffu, d0[1], srclane);
        float g1_1 = __shfl_sync(0xffffffffu, d1[1], srclane);
        float g0_2 = __shfl_sync(0xffffffffu, d0[2], srclane);
        float g1_2 = __shfl_sync(0xffffffffu, d1[2], srclane);
        float g0_3 = __shfl_sync(0xffffffffu, d0[3], srclane);
        float g1_3 = __shfl_sync(0xffffffffu, d1[3], srclane);

        float p0 = subsel ? g1_0 : g0_0;
        float p1 = subsel ? g1_1 : g0_1;
        float p2 = subsel ? g1_2 : g0_2;
        float p3 = subsel ? g1_3 : g0_3;
        float q0 = tilesel0 ? p1 : p0;
        float q1 = tilesel0 ? p3 : p2;
        float z  = (tilesel1 ? q1 : q0) + zp_cur;

        // ---- Activation (warps 8..11 own the g gate: tanh; else sigmoid) ----
        float a = (w >= 8 && w < 12) ? tanh_f(z) : sigm(z);
        act[mycol] = a;
        __syncthreads();

        // ---- c/h update: one thread per hidden unit ----
        if (tid < F_) {
            float ig = act[tid];
            float fg = act[F_ + tid];
            float gg = act[2 * F_ + tid];
            float og = act[3 * F_ + tid];
            float cn = fmaf(fg, c_reg, ig * gg);
            c_reg = cn;
            float hn = og * tanh_f(cn);
            out_row[(size_t)t * F_ + tid] = hn;
            hs[tid] = __float2half_rn(hn);
        }
        __syncthreads();

        zp_cur = zp_next;
    }
}

// ---------------------------------------------------------------------------
// kernel_launch: inputs in metadata order x, h0, c0, Wi, Wh, b.
// ---------------------------------------------------------------------------
extern "C" void kernel_launch(void* const* d_in, const int* in_sizes, int n_in,
                              void* d_out, int out_size) {
    const float* x    = (const float*)d_in[0];  // (64, 2048, 128)
    const float* h0   = (const float*)d_in[1];  // (64, 128)
    const float* c0   = (const float*)d_in[2];  // (64, 128)
    const float* Wi   = (const float*)d_in[3];  // (128, 512)
    const float* Wh   = (const float*)d_in[4];  // (128, 512)
    const float* bias = (const float*)d_in[5];  // (512)
    float* out = (float*)d_out;                 // (64, 2048, 128)

    // Allow 68 KB dynamic shared for the tensor GEMM (idempotent).
    cudaFuncSetAttribute(gemm_xwi_h, cudaFuncAttributeMaxDynamicSharedMemorySize,
                         GEMM_SMEM);

    // Input projection: (131072 x 128) @ (128 x 512) + b  -> g_zpre (HMMA)
    gemm_xwi_h<<<dim3((B_ * T_) / 128, G4 / 128), 256, GEMM_SMEM>>>(x, Wi, bias);

    // Recurrence: 64 persistent CTAs, one per batch row.
    lstm_rec<<<B_, 512>>>(Wh, h0, c0, out);
}

// round 13
// speedup vs baseline: 1.8751x; 1.0174x over previous
#include <cuda_runtime.h>
#include <cuda_fp16.h>

// Problem constants
#define B_   64
#define T_   2048
#define D_   128
#define F_   128
#define G4   512   // 4*F

// Scratch for precomputed input projection Zpre = X @ Wi + b  (256 MB)
__device__ float g_zpre[(size_t)B_ * T_ * G4];

__device__ __forceinline__ void mma16816(float& d0, float& d1, float& d2, float& d3,
                                         unsigned a0, unsigned a1, unsigned a2, unsigned a3,
                                         unsigned b0, unsigned b1) {
    asm volatile(
        "mma.sync.aligned.m16n8k16.row.col.f32.f16.f16.f32 "
        "{%0,%1,%2,%3}, {%4,%5,%6,%7}, {%8,%9}, {%0,%1,%2,%3};\n"
        : "+f"(d0), "+f"(d1), "+f"(d2), "+f"(d3)
        : "r"(a0), "r"(a1), "r"(a2), "r"(a3), "r"(b0), "r"(b1));
}

// ---------------------------------------------------------------------------
// Kernel A: Zpre = X @ Wi + b via fp16 HMMA (unchanged from R8 — verified).
// ---------------------------------------------------------------------------
#define ASTRIDE 136                       // halves per row (128 + 8 pad)
#define GEMM_SMEM (2 * 128 * ASTRIDE * 2) // 69632 bytes

__global__ __launch_bounds__(256) void gemm_xwi_h(const float* __restrict__ X,
                                                  const float* __restrict__ Wi,
                                                  const float* __restrict__ bias) {
    extern __shared__ __half sm[];
    __half* As = sm;                   // [128][ASTRIDE]  (m, k)
    __half* Bs = sm + 128 * ASTRIDE;   // [128][ASTRIDE]  (n, k)  = Wi^T
    const int mblk = blockIdx.x * 128;
    const int nblk = blockIdx.y * 128;
    const int tid  = threadIdx.x;

#pragma unroll
    for (int i = 0; i < 16; i++) {
        int f4 = tid + i * 256;
        int m  = f4 >> 5;
        int q  = f4 & 31;
        float4 v = *(const float4*)(X + (size_t)(mblk + m) * D_ + q * 4);
        __half2 h0 = __floats2half2_rn(v.x, v.y);
        __half2 h1 = __floats2half2_rn(v.z, v.w);
        uint2 u; u.x = *(unsigned*)&h0; u.y = *(unsigned*)&h1;
        *(uint2*)(As + m * ASTRIDE + q * 4) = u;
    }
#pragma unroll
    for (int i = 0; i < 16; i++) {
        int f4 = tid + i * 256;
        int k  = f4 >> 5;
        int q  = f4 & 31;
        float4 v = *(const float4*)(Wi + (size_t)k * G4 + nblk + q * 4);
        Bs[(q * 4 + 0) * ASTRIDE + k] = __float2half_rn(v.x);
        Bs[(q * 4 + 1) * ASTRIDE + k] = __float2half_rn(v.y);
        Bs[(q * 4 + 2) * ASTRIDE + k] = __float2half_rn(v.z);
        Bs[(q * 4 + 3) * ASTRIDE + k] = __float2half_rn(v.w);
    }
    __syncthreads();

    const int w  = tid >> 5, l = tid & 31;
    const int wm = w >> 1;
    const int wn = w & 1;
    const int g  = l >> 2, t = l & 3;

    float acc[2][8][4];
#pragma unroll
    for (int ms = 0; ms < 2; ms++)
#pragma unroll
        for (int ns = 0; ns < 8; ns++)
#pragma unroll
            for (int j = 0; j < 4; j++) acc[ms][ns][j] = 0.f;

    const unsigned* As2 = (const unsigned*)As;
    const unsigned* Bs2 = (const unsigned*)Bs;
#define HSTR (ASTRIDE / 2)

#pragma unroll
    for (int kc = 0; kc < 8; kc++) {
        const int kw = kc * 8 + t;
        unsigned a[2][4];
#pragma unroll
        for (int ms = 0; ms < 2; ms++) {
            int r = wm * 32 + ms * 16 + g;
            a[ms][0] = As2[(size_t)r * HSTR + kw];
            a[ms][1] = As2[(size_t)(r + 8) * HSTR + kw];
            a[ms][2] = As2[(size_t)r * HSTR + kw + 4];
            a[ms][3] = As2[(size_t)(r + 8) * HSTR + kw + 4];
        }
#pragma unroll
        for (int ns = 0; ns < 8; ns++) {
            int n = wn * 64 + ns * 8 + g;
            unsigned b0 = Bs2[(size_t)n * HSTR + kw];
            unsigned b1 = Bs2[(size_t)n * HSTR + kw + 4];
#pragma unroll
            for (int ms = 0; ms < 2; ms++)
                mma16816(acc[ms][ns][0], acc[ms][ns][1], acc[ms][ns][2], acc[ms][ns][3],
                         a[ms][0], a[ms][1], a[ms][2], a[ms][3], b0, b1);
        }
    }

#pragma unroll
    for (int ms = 0; ms < 2; ms++) {
        int r0 = mblk + wm * 32 + ms * 16 + g;
#pragma unroll
        for (int ns = 0; ns < 8; ns++) {
            int col = nblk + wn * 64 + ns * 8 + 2 * t;
            float2 bv = *(const float2*)(bias + col);
            float2 o0 = make_float2(acc[ms][ns][0] + bv.x, acc[ms][ns][1] + bv.y);
            float2 o1 = make_float2(acc[ms][ns][2] + bv.x, acc[ms][ns][3] + bv.y);
            *(float2*)(g_zpre + (size_t)r0 * G4 + col)       = o0;
            *(float2*)(g_zpre + (size_t)(r0 + 8) * G4 + col) = o1;
        }
    }
}

// ---------------------------------------------------------------------------
// Kernel B: persistent recurrent LSTM, HMMA, gate-interleaved columns.
// Warp w owns gates {i,f,g,o} of hidden units [8w, 8w+8):
//   n-tile tt = gate tt, global column = tt*128 + 8w + gid.
// After shfl routing, lane l holds gate (l>>3) of unit 8w + (l&7) -> the
// whole c/h update is intra-warp (4 shfls). One barrier per step, with
// double-buffered fp16 h state. Activations via MUFU tanh.approx.
// ---------------------------------------------------------------------------

__device__ __forceinline__ float tanh_a(float x) {
    float y;
    asm("tanh.approx.f32 %0, %1;" : "=f"(y) : "f"(x));
    return y;
}
__device__ __forceinline__ float sigm_a(float x) {
    return fmaf(0.5f, tanh_a(0.5f * x), 0.5f);
}

__global__ __launch_bounds__(512, 1) void lstm_rec(const float* __restrict__ Wh,
                                                   const float* __restrict__ h0,
                                                   const float* __restrict__ c0,
                                                   float* __restrict__ out) {
    __shared__ __align__(16) __half hsbuf[2][F_];   // double-buffered hidden state

    const int b   = blockIdx.x;
    const int tid = threadIdx.x;
    const int w   = tid >> 5;          // warp 0..15
    const int l   = tid & 31;          // lane
    const int t4  = l & 3;
    const int gid = l >> 2;

    // ---- Load Wh into register-resident B fragments (fp32 -> fp16) ----
    // Gate-interleaved: tile tt -> gate tt, units 8w..8w+7.
    unsigned b0r[4][8], b1r[4][8];
#pragma unroll
    for (int tt = 0; tt < 4; tt++) {
        const int col = tt * 128 + w * 8 + gid;
#pragma unroll
        for (int kc = 0; kc < 8; kc++) {
            const int k0 = kc * 16 + 2 * t4;
            __half2 p0 = __floats2half2_rn(Wh[(size_t)k0 * G4 + col],
                                           Wh[(size_t)(k0 + 1) * G4 + col]);
            __half2 p1 = __floats2half2_rn(Wh[(size_t)(k0 + 8) * G4 + col],
                                           Wh[(size_t)(k0 + 9) * G4 + col]);
            b0r[tt][kc] = *(unsigned*)&p0;
            b1r[tt][kc] = *(unsigned*)&p1;
        }
    }

    // ---- Init state ----
    float c_reg = 0.f;
    if (l < 8) c_reg = c0[b * F_ + w * 8 + l];     // lane l<8 owns unit 8w+l
    if (tid < F_) hsbuf[0][tid] = __float2half_rn(h0[b * F_ + tid]);
    __syncthreads();

    const float* zp_base = g_zpre + (size_t)b * T_ * G4;
    float*       out_row = out    + (size_t)b * T_ * F_;

    // This lane's routed value: gate (l>>3), unit 8w + (l&7).
    const int mycol    = (l >> 3) * 128 + w * 8 + (l & 7);
    const int mygate   = l >> 3;
    const int tilesel0 = (l >> 3) & 1;
    const int tilesel1 = (l >> 4) & 1;
    const int subsel   = l & 1;
    const int srclane  = (l & 7) >> 1;
    const int u        = l & 7;        // unit index for the gather shfls

    float zp_cur = __ldg(zp_base + mycol);
    int p = 0;

    for (int t = 0; t < T_; t++) {
        const int tn = (t + 1 < T_) ? (t + 1) : t;
        float zp_next = __ldg(zp_base + (size_t)tn * G4 + mycol);

        // ---- z = h @ Wh (row 0 of D), h from current parity buffer ----
        const unsigned* hs2 = (const unsigned*)hsbuf[p];
        float d0[4], d1[4], d2[4], d3[4];
#pragma unroll
        for (int tt = 0; tt < 4; tt++) { d0[tt] = 0.f; d1[tt] = 0.f; d2[tt] = 0.f; d3[tt] = 0.f; }

#pragma unroll
        for (int kc = 0; kc < 8; kc++) {
            unsigned a0 = hs2[kc * 8 + t4];
            unsigned a2 = hs2[kc * 8 + 4 + t4];
#pragma unroll
            for (int tt = 0; tt < 4; tt++)
                mma16816(d0[tt], d1[tt], d2[tt], d3[tt], a0, a0, a2, a2,
                         b0r[tt][kc], b1r[tt][kc]);
        }

        // ---- Route row-0 values: lane l gets local col l (gate l>>3, unit u) ----
        float g0_0 = __shfl_sync(0xffffffffu, d0[0], srclane);
        float g1_0 = __shfl_sync(0xffffffffu, d1[0], srclane);
        float g0_1 = __shfl_sync(0xffffffffu, d0[1], srclane);
        float g1_1 = __shfl_sync(0xffffffffu, d1[1], srclane);
        float g0_2 = __shfl_sync(0xffffffffu, d0[2], srclane);
        float g1_2 = __shfl_sync(0xffffffffu, d1[2], srclane);
        float g0_3 = __shfl_sync(0xffffffffu, d0[3], srclane);
        float g1_3 = __shfl_sync(0xffffffffu, d1[3], srclane);

        float p0 = subsel ? g1_0 : g0_0;
        float p1 = subsel ? g1_1 : g0_1;
        float p2 = subsel ? g1_2 : g0_2;
        float p3 = subsel ? g1_3 : g0_3;
        float q0 = tilesel0 ? p1 : p0;
        float q1 = tilesel0 ? p3 : p2;
        float z  = (tilesel1 ? q1 : q0) + zp_cur;

        // ---- Activation: gate 2 (g) -> tanh, else sigmoid ----
        float a = (mygate == 2) ? tanh_a(z) : sigm_a(z);

        // ---- Gather 4 gates of unit u to lanes 0..7 ----
        float ig = __shfl_sync(0xffffffffu, a, u);
        float fg = __shfl_sync(0xffffffffu, a, u + 8);
        float gg = __shfl_sync(0xffffffffu, a, u + 16);
        float og = __shfl_sync(0xffffffffu, a, u + 24);

        if (l < 8) {
            float cn = fmaf(fg, c_reg, ig * gg);
            c_reg = cn;
            float hn = og * tanh_a(cn);
            out_row[(size_t)t * F_ + w * 8 + l] = hn;
            hsbuf[p ^ 1][w * 8 + l] = __float2half_rn(hn);
        }
        __syncthreads();

        p ^= 1;
        zp_cur = zp_next;
    }
}

// ---------------------------------------------------------------------------
// kernel_launch: inputs in metadata order x, h0, c0, Wi, Wh, b.
// ---------------------------------------------------------------------------
extern "C" void kernel_launch(void* const* d_in, const int* in_sizes, int n_in,
                              void* d_out, int out_size) {
    const float* x    = (const float*)d_in[0];  // (64, 2048, 128)
    const float* h0   = (const float*)d_in[1];  // (64, 128)
    const float* c0   = (const float*)d_in[2];  // (64, 128)
    const float* Wi   = (const float*)d_in[3];  // (128, 512)
    const float* Wh   = (const float*)d_in[4];  // (128, 512)
    const float* bias = (const float*)d_in[5];  // (512)
    float* out = (float*)d_out;                 // (64, 2048, 128)

    cudaFuncSetAttribute(gemm_xwi_h, cudaFuncAttributeMaxDynamicSharedMemorySize,
                         GEMM_SMEM);

    // Input projection: (131072 x 128) @ (128 x 512) + b  -> g_zpre (HMMA)
    gemm_xwi_h<<<dim3((B_ * T_) / 128, G4 / 128), 256, GEMM_SMEM>>>(x, Wi, bias);

    // Recurrence: 64 persistent CTAs, one per batch row.
    lstm_rec<<<B_, 512>>>(Wh, h0, c0, out);
}